// round 6
// baseline (speedup 1.0000x reference)
#include <cuda_runtime.h>
#include <cuda_fp16.h>
#include <cstdint>

#define DB 4096   // batch rows
#define DL 4096   // labels
#define DH 1024   // hidden

#define TILE_M 128
#define TILE_N 256
#define KCH 64
#define NCHUNK (DH / KCH)   // 16
#define STAGES 3

// per-stage smem: AH(16K) AL(16K) B(32K) — rows of 64 fp16 = 128B, SW128 swizzle
#define ST_AH 0
#define ST_AL 16384
#define ST_B  32768
#define STAGE_BYTES 65536
#define SMEM_DYN (STAGES * STAGE_BYTES)   // 196608 -> 1 CTA/SM

// ---------------- scratch (static device arrays: allowed) ----------------
__device__ __half g_xhi[(size_t)DB * DH];
__device__ __half g_xlo[(size_t)DB * DH];
__device__ __half g_w[(size_t)DL * DH];
__device__ float g_diag[DL];

// ---------------- helpers ----------------
__device__ __forceinline__ uint32_t smem_u32(const void* p) {
    uint32_t a;
    asm("{ .reg .u64 t; cvta.to.shared.u64 t, %1; cvt.u32.u64 %0, t; }" : "=r"(a) : "l"(p));
    return a;
}
__device__ __forceinline__ uint32_t swz(uint32_t b) {   // SW128: 16B chunk ^= row%8
    return b ^ ((b >> 3) & 0x70);
}
__device__ __forceinline__ void cp16(uint32_t dst, const void* gsrc) {
    asm volatile("cp.async.cg.shared.global [%0], [%1], 16;" :: "r"(dst), "l"(gsrc));
}
__device__ __forceinline__ void cp_commit() {
    asm volatile("cp.async.commit_group;");
}
__device__ __forceinline__ void cp_wait2() {
    asm volatile("cp.async.wait_group 2;");
}
__device__ __forceinline__ void ldm_x4(uint32_t addr, uint32_t* r) {
    asm volatile("ldmatrix.sync.aligned.m8n8.x4.shared.b16 {%0,%1,%2,%3}, [%4];"
                 : "=r"(r[0]), "=r"(r[1]), "=r"(r[2]), "=r"(r[3]) : "r"(addr));
}
__device__ __forceinline__ void mma4(float* c, const uint32_t* a, uint32_t b0, uint32_t b1) {
    asm volatile(
        "mma.sync.aligned.m16n8k16.row.col.f32.f16.f16.f32 "
        "{%0,%1,%2,%3},{%4,%5,%6,%7},{%8,%9},{%0,%1,%2,%3};"
        : "+f"(c[0]), "+f"(c[1]), "+f"(c[2]), "+f"(c[3])
        : "r"(a[0]), "r"(a[1]), "r"(a[2]), "r"(a[3]), "r"(b0), "r"(b1));
}

// ---------------- convert kernels ----------------
__device__ __forceinline__ void split1h(float v, unsigned short& h, unsigned short& l) {
    __half hh = __float2half_rn(v);
    float r = v - __half2float(hh);
    __half hl = __float2half_rn(r);
    h = __half_as_ushort(hh);
    l = __half_as_ushort(hl);
}

__global__ void __launch_bounds__(256) k_split_x(const float* __restrict__ x) {
    size_t i = (size_t)blockIdx.x * blockDim.x + threadIdx.x;  // one float4 each
    float4 v = reinterpret_cast<const float4*>(x)[i];
    ushort4 h, l;
    split1h(v.x, h.x, l.x);
    split1h(v.y, h.y, l.y);
    split1h(v.z, h.z, l.z);
    split1h(v.w, h.w, l.w);
    reinterpret_cast<ushort4*>(g_xhi)[i] = h;
    reinterpret_cast<ushort4*>(g_xlo)[i] = l;
}

__global__ void __launch_bounds__(256) k_split_w_diag(const float* __restrict__ W,
                                                      const float* __restrict__ E,
                                                      const float* __restrict__ b) {
    int j = blockIdx.x;                  // label row
    int t = threadIdx.x;                 // 256 threads, 1 float4 each (1024 cols)
    size_t i4 = (size_t)j * 256 + t;
    float4 w = reinterpret_cast<const float4*>(W)[i4];
    float4 e = reinterpret_cast<const float4*>(E)[i4];
    ushort4 h;
    h.x = __half_as_ushort(__float2half_rn(w.x));
    h.y = __half_as_ushort(__float2half_rn(w.y));
    h.z = __half_as_ushort(__float2half_rn(w.z));
    h.w = __half_as_ushort(__float2half_rn(w.w));
    reinterpret_cast<ushort4*>(g_w)[i4] = h;

    float acc = w.x * e.x + w.y * e.y + w.z * e.z + w.w * e.w;
    #pragma unroll
    for (int o = 16; o > 0; o >>= 1) acc += __shfl_xor_sync(0xFFFFFFFFu, acc, o);
    __shared__ float red[8];
    if ((t & 31) == 0) red[t >> 5] = acc;
    __syncthreads();
    if (t == 0) {
        float s = 0.f;
        #pragma unroll
        for (int k = 0; k < 8; k++) s += red[k];
        g_diag[j] = s + b[j];
    }
}

// ---------------- GEMM kernel: 128x256 CTA, 64x64 warp tile, 3-stage ------
__global__ void __launch_bounds__(256, 1) k_gemm(float* __restrict__ out) {
    extern __shared__ char smraw[];
    const uint32_t sb = smem_u32(smraw);
    const int tid = threadIdx.x;
    const int lane = tid & 31;
    const int wid = tid >> 5;
    const int warpM = wid & 1;   // 2 warps in M (64 rows each)
    const int warpN = wid >> 1;  // 4 warps in N (64 cols each)
    const int row0 = blockIdx.y * TILE_M;
    const int col0 = blockIdx.x * TILE_N;

    const char* gxh = (const char*)g_xhi;
    const char* gxl = (const char*)g_xlo;
    const char* gw  = (const char*)g_w;

    // ---- async copy of one K-chunk into a stage slot (16K + 16K + 32K) ----
    auto issue = [&](int chunk) {
        const int kc = chunk * KCH;
        const uint32_t sst = sb + (chunk % STAGES) * STAGE_BYTES;
        #pragma unroll
        for (int j = 0; j < 8; j++) {      // xhi (j<4), xlo (j>=4): 128 rows each
            const int arr = j >> 2;
            const int t = (j & 3) * 256 + tid;
            const int row = t >> 3;
            const int c16 = t & 7;
            const char* gb = (arr == 0) ? gxh : gxl;
            const char* src = gb + ((size_t)(row0 + row) * DH + kc + c16 * 8) * 2;
            const uint32_t dst = sst + arr * 16384 + swz(row * 128 + c16 * 16);
            cp16(dst, src);
        }
        #pragma unroll
        for (int j = 0; j < 8; j++) {      // w: 256 rows
            const int t = j * 256 + tid;   // 0..2047
            const int row = t >> 3;
            const int c16 = t & 7;
            const char* src = gw + ((size_t)(col0 + row) * DH + kc + c16 * 8) * 2;
            const uint32_t dst = sst + ST_B + swz(row * 128 + c16 * 16);
            cp16(dst, src);
        }
    };

    float acc[4][8][4];
    #pragma unroll
    for (int mt = 0; mt < 4; mt++)
        #pragma unroll
        for (int nt = 0; nt < 8; nt++)
            #pragma unroll
            for (int q = 0; q < 4; q++) acc[mt][nt][q] = 0.f;

    issue(0); cp_commit();
    issue(1); cp_commit();
    issue(2); cp_commit();

    const int lrow = lane & 15;
    const int lhalf = (lane >> 4) << 4;

    for (int c = 0; c < NCHUNK; c++) {
        cp_wait2();
        __syncthreads();

        const uint32_t s0 = sb + (c % STAGES) * STAGE_BYTES;
        #pragma unroll
        for (int ks = 0; ks < 4; ks++) {
            const uint32_t lsw = swz((uint32_t)(lrow * 128 + ks * 32 + lhalf));
            const uint32_t abase = s0 + ST_AH + warpM * 8192 + lsw;   // 64 rows * 128B
            const uint32_t bbase = s0 + ST_B + warpN * 8192 + lsw;    // 64 rows * 128B

            uint32_t bb[4][4];
            #pragma unroll
            for (int g = 0; g < 4; g++) ldm_x4(bbase + g * 2048, bb[g]);

            #pragma unroll
            for (int mt = 0; mt < 4; mt++) {
                uint32_t ah[4], al[4];
                ldm_x4(abase + mt * 2048, ah);
                ldm_x4(abase + (ST_AL - ST_AH) + mt * 2048, al);
                #pragma unroll
                for (int nt = 0; nt < 8; nt++) {
                    const int g = nt >> 1, p = nt & 1;
                    mma4(acc[mt][nt], ah, bb[g][p], bb[g][p + 2]);   // xhi * w
                    mma4(acc[mt][nt], al, bb[g][p], bb[g][p + 2]);   // xlo * w
                }
            }
        }

        __syncthreads();                 // all warps done with slot c%3
        if (c + 3 < NCHUNK) issue(c + 3);
        cp_commit();                     // (possibly empty) group keeps wait_group 2 correct
    }

    // ---- epilogue: add diag bias, store float2 pairs ----
    const int gid = lane >> 2;
    const int qid = lane & 3;
    #pragma unroll
    for (int mt = 0; mt < 4; mt++) {
        #pragma unroll
        for (int nt = 0; nt < 8; nt++) {
            const int m = row0 + warpM * 64 + mt * 16 + gid;
            const int n = col0 + warpN * 64 + nt * 8 + qid * 2;
            const float2 d = *reinterpret_cast<const float2*>(&g_diag[n]);
            float2 v0, v1;
            v0.x = acc[mt][nt][0] + d.x;
            v0.y = acc[mt][nt][1] + d.y;
            v1.x = acc[mt][nt][2] + d.x;
            v1.y = acc[mt][nt][3] + d.y;
            *reinterpret_cast<float2*>(&out[(size_t)m * DL + n]) = v0;
            *reinterpret_cast<float2*>(&out[(size_t)(m + 8) * DL + n]) = v1;
        }
    }
}

// ---------------- host ----------------
extern "C" void kernel_launch(void* const* d_in, const int* in_sizes, int n_in,
                              void* d_out, int out_size) {
    (void)in_sizes; (void)n_in; (void)out_size;
    const float* x = (const float*)d_in[0];
    const float* E = (const float*)d_in[1];
    const float* W = (const float*)d_in[2];
    const float* b = (const float*)d_in[3];
    float* out = (float*)d_out;

    k_split_x<<<(DB * DH / 4) / 256, 256>>>(x);
    k_split_w_diag<<<DL, 256>>>(W, E, b);

    cudaFuncSetAttribute(k_gemm, cudaFuncAttributeMaxDynamicSharedMemorySize, SMEM_DYN);

    dim3 grid(DL / TILE_N, DB / TILE_M);   // (16, 32)
    k_gemm<<<grid, 256, SMEM_DYN>>>(out);
}

// round 7
// speedup vs baseline: 1.9882x; 1.9882x over previous
#include <cuda_runtime.h>
#include <cuda_fp16.h>
#include <cstdint>

#define DB 4096   // batch rows
#define DL 4096   // labels
#define DH 1024   // hidden

#define TILE_M 128
#define TILE_N 128
#define KCH 64
#define NCHUNK (DH / KCH)   // 16
#define STAGES 3

// per-stage smem: A(16K) B(16K) — rows of 64 fp16 = 128B, SW128 swizzle
#define ST_A 0
#define ST_B 16384
#define STAGE_BYTES 32768
#define SMEM_DYN (STAGES * STAGE_BYTES)   // 98304 -> 2 CTAs/SM

// ---------------- scratch (static device arrays: allowed) ----------------
__device__ __half g_x[(size_t)DB * DH];
__device__ __half g_w[(size_t)DL * DH];
__device__ float g_diag[DL];

// ---------------- helpers ----------------
__device__ __forceinline__ uint32_t smem_u32(const void* p) {
    uint32_t a;
    asm("{ .reg .u64 t; cvta.to.shared.u64 t, %1; cvt.u32.u64 %0, t; }" : "=r"(a) : "l"(p));
    return a;
}
__device__ __forceinline__ uint32_t swz(uint32_t b) {   // SW128: 16B chunk ^= row%8
    return b ^ ((b >> 3) & 0x70);
}
__device__ __forceinline__ void cp16(uint32_t dst, const void* gsrc) {
    asm volatile("cp.async.cg.shared.global [%0], [%1], 16;" :: "r"(dst), "l"(gsrc));
}
__device__ __forceinline__ void cp_commit() {
    asm volatile("cp.async.commit_group;");
}
__device__ __forceinline__ void cp_wait1() {
    asm volatile("cp.async.wait_group 1;");
}
__device__ __forceinline__ void ldm_x4(uint32_t addr, uint32_t* r) {
    asm volatile("ldmatrix.sync.aligned.m8n8.x4.shared.b16 {%0,%1,%2,%3}, [%4];"
                 : "=r"(r[0]), "=r"(r[1]), "=r"(r[2]), "=r"(r[3]) : "r"(addr));
}
__device__ __forceinline__ void mma4(float* c, const uint32_t* a, uint32_t b0, uint32_t b1) {
    asm volatile(
        "mma.sync.aligned.m16n8k16.row.col.f32.f16.f16.f32 "
        "{%0,%1,%2,%3},{%4,%5,%6,%7},{%8,%9},{%0,%1,%2,%3};"
        : "+f"(c[0]), "+f"(c[1]), "+f"(c[2]), "+f"(c[3])
        : "r"(a[0]), "r"(a[1]), "r"(a[2]), "r"(a[3]), "r"(b0), "r"(b1));
}

// ---------------- convert kernels ----------------
__global__ void __launch_bounds__(256) k_conv_x(const float* __restrict__ x) {
    size_t i = (size_t)blockIdx.x * blockDim.x + threadIdx.x;  // one float4 each
    float4 v = reinterpret_cast<const float4*>(x)[i];
    ushort4 h;
    h.x = __half_as_ushort(__float2half_rn(v.x));
    h.y = __half_as_ushort(__float2half_rn(v.y));
    h.z = __half_as_ushort(__float2half_rn(v.z));
    h.w = __half_as_ushort(__float2half_rn(v.w));
    reinterpret_cast<ushort4*>(g_x)[i] = h;
}

__global__ void __launch_bounds__(256) k_conv_w_diag(const float* __restrict__ W,
                                                     const float* __restrict__ E,
                                                     const float* __restrict__ b) {
    int j = blockIdx.x;                  // label row
    int t = threadIdx.x;                 // 256 threads, 1 float4 each (1024 cols)
    size_t i4 = (size_t)j * 256 + t;
    float4 w = reinterpret_cast<const float4*>(W)[i4];
    float4 e = reinterpret_cast<const float4*>(E)[i4];
    ushort4 h;
    h.x = __half_as_ushort(__float2half_rn(w.x));
    h.y = __half_as_ushort(__float2half_rn(w.y));
    h.z = __half_as_ushort(__float2half_rn(w.z));
    h.w = __half_as_ushort(__float2half_rn(w.w));
    reinterpret_cast<ushort4*>(g_w)[i4] = h;

    float acc = w.x * e.x + w.y * e.y + w.z * e.z + w.w * e.w;
    #pragma unroll
    for (int o = 16; o > 0; o >>= 1) acc += __shfl_xor_sync(0xFFFFFFFFu, acc, o);
    __shared__ float red[8];
    if ((t & 31) == 0) red[t >> 5] = acc;
    __syncthreads();
    if (t == 0) {
        float s = 0.f;
        #pragma unroll
        for (int k = 0; k < 8; k++) s += red[k];
        g_diag[j] = s + b[j];
    }
}

// ------- GEMM: 128x128 CTA, 64x32 warp tile, 3-stage, 1 sync/chunk --------
__global__ void __launch_bounds__(256, 2) k_gemm(float* __restrict__ out) {
    extern __shared__ char smraw[];
    const uint32_t sb = smem_u32(smraw);
    const int tid = threadIdx.x;
    const int lane = tid & 31;
    const int wid = tid >> 5;
    const int warpM = wid & 1;   // 2 warps in M (64 rows each)
    const int warpN = wid >> 1;  // 4 warps in N (32 cols each)
    const int row0 = blockIdx.y * TILE_M;
    const int col0 = blockIdx.x * TILE_N;

    const char* gx = (const char*)g_x;
    const char* gw = (const char*)g_w;

    // ---- async copy of one K-chunk into a stage slot (16K A + 16K B) ----
    auto issue = [&](int chunk) {
        const int kc = chunk * KCH;
        const uint32_t sst = sb + (chunk % STAGES) * STAGE_BYTES;
        #pragma unroll
        for (int j = 0; j < 8; j++) {
            const int arr = j >> 2;                        // 0: x(A), 1: w(B)
            const int t = (j & 3) * 256 + tid;             // 0..1023
            const int row = t >> 3;                        // 0..127
            const int c16 = t & 7;                         // 16B chunk in 128B row
            const int rb = (arr == 0) ? row0 : col0;
            const char* gb = (arr == 0) ? gx : gw;
            const char* src = gb + ((size_t)(rb + row) * DH + kc + c16 * 8) * 2;
            const uint32_t dst = sst + arr * 16384 + swz(row * 128 + c16 * 16);
            cp16(dst, src);
        }
    };

    float acc[4][4][4];
    #pragma unroll
    for (int mt = 0; mt < 4; mt++)
        #pragma unroll
        for (int nt = 0; nt < 4; nt++)
            #pragma unroll
            for (int q = 0; q < 4; q++) acc[mt][nt][q] = 0.f;

    issue(0); cp_commit();
    issue(1); cp_commit();

    const int lrow = lane & 15;
    const int lhalf = (lane >> 4) << 4;

    for (int c = 0; c < NCHUNK; c++) {
        cp_wait1();                      // chunk c landed (c+1 may be in flight)
        __syncthreads();                 // also: everyone done with slot (c+2)%3 (read in iter c-1)
        if (c + 2 < NCHUNK) issue(c + 2);
        cp_commit();                     // empty group at tail keeps wait_group 1 uniform

        const uint32_t s0 = sb + (c % STAGES) * STAGE_BYTES;
        #pragma unroll
        for (int ks = 0; ks < 4; ks++) {
            const uint32_t lsw = swz((uint32_t)(lrow * 128 + ks * 32 + lhalf));
            const uint32_t abase = s0 + ST_A + warpM * 8192 + lsw;   // 64 rows * 128B
            const uint32_t bbase = s0 + ST_B + warpN * 4096 + lsw;   // 32 rows * 128B

            uint32_t bb[2][4];
            ldm_x4(bbase, bb[0]);
            ldm_x4(bbase + 2048, bb[1]);                 // +16 n-rows

            #pragma unroll
            for (int mt = 0; mt < 4; mt++) {
                uint32_t aa[4];
                ldm_x4(abase + mt * 2048, aa);
                #pragma unroll
                for (int nt = 0; nt < 4; nt++) {
                    const int r = nt >> 1, p = nt & 1;
                    mma4(acc[mt][nt], aa, bb[r][p], bb[r][p + 2]);
                }
            }
        }
    }

    // ---- epilogue: add diag bias, store float2 pairs ----
    const int gid = lane >> 2;
    const int qid = lane & 3;
    #pragma unroll
    for (int mt = 0; mt < 4; mt++) {
        #pragma unroll
        for (int nt = 0; nt < 4; nt++) {
            const int m = row0 + warpM * 64 + mt * 16 + gid;
            const int n = col0 + warpN * 32 + nt * 8 + qid * 2;
            const float2 d = *reinterpret_cast<const float2*>(&g_diag[n]);
            float2 v0, v1;
            v0.x = acc[mt][nt][0] + d.x;
            v0.y = acc[mt][nt][1] + d.y;
            v1.x = acc[mt][nt][2] + d.x;
            v1.y = acc[mt][nt][3] + d.y;
            *reinterpret_cast<float2*>(&out[(size_t)m * DL + n]) = v0;
            *reinterpret_cast<float2*>(&out[(size_t)(m + 8) * DL + n]) = v1;
        }
    }
}

// ---------------- host ----------------
extern "C" void kernel_launch(void* const* d_in, const int* in_sizes, int n_in,
                              void* d_out, int out_size) {
    (void)in_sizes; (void)n_in; (void)out_size;
    const float* x = (const float*)d_in[0];
    const float* E = (const float*)d_in[1];
    const float* W = (const float*)d_in[2];
    const float* b = (const float*)d_in[3];
    float* out = (float*)d_out;

    k_conv_x<<<(DB * DH / 4) / 256, 256>>>(x);
    k_conv_w_diag<<<DL, 256>>>(W, E, b);

    cudaFuncSetAttribute(k_gemm, cudaFuncAttributeMaxDynamicSharedMemorySize, SMEM_DYN);

    dim3 grid(DL / TILE_N, DB / TILE_M);   // (32, 32)
    k_gemm<<<grid, 256, SMEM_DYN>>>(out);
}